// round 1
// baseline (speedup 1.0000x reference)
#include <cuda_runtime.h>

// Problem constants
#define NB 1024   // batches
#define NT 256    // timesteps
#define NS 16     // states
#define NM 4      // measurements
#define NSTEP 255 // scan steps (T-1)
#define ROWF 20   // padded shared row (80B, 16B aligned)

// Precomputed per-step affine maps:
// blob[t] is 20 rows x 20 floats: row g<16: [A_t[g][0..15] | B_t[g][0..3]]
//                                 row 16+m: [HA_t[m][0..15] | HB_t[m][0..3]]
__device__ float4 g_blob[NSTEP * 100];  // 255 * 400 floats = 408 KB
__device__ float  g_s0[16];             // initial predicted state (same for all batches)
__device__ float  g_y0[4];              // H @ s0 (output at t=0, same for all batches)

// ---------------------------------------------------------------------------
// Phase 1: sequential Riccati recursion, ONE block of 256 threads.
// Thread tid -> element (i = tid/16, j = tid%16) of 16x16 matrices.
// Per step:
//   HP = H P ; S = HP H^T + R ; Sinv (4x4 cofactors, 16 threads)
//   K  = (HP)^T Sinv ; L = F K ; A = F - L H ; LR = L R
//   T1 = A P ; HA = H A ; HB = H L
//   P' = T1 A^T + LR L^T + Q ; store [A|L;HA|HB] to blob
// ---------------------------------------------------------------------------
__global__ __launch_bounds__(256, 1) void riccati_kernel(
    const float* __restrict__ F, const float* __restrict__ H,
    const float* __restrict__ Q, const float* __restrict__ R,
    const float* __restrict__ x0, const float* __restrict__ sd)
{
    __shared__ float sP[16][ROWF];
    __shared__ float sT[16][ROWF];
    __shared__ float sA[16][ROWF];
    __shared__ float sF[16][ROWF];
    __shared__ float sQ[16][ROWF];
    __shared__ float sH[4][ROWF];
    __shared__ float sHP[4][ROWF];
    __shared__ float sHA[4][ROWF];
    __shared__ __align__(16) float sK[16][4];
    __shared__ __align__(16) float sL[16][4];
    __shared__ __align__(16) float sLR[16][4];
    __shared__ float sS[4][4];
    __shared__ float sSi[4][4];
    __shared__ float sR[4][4];
    __shared__ float sHB[4][4];
    __shared__ float scof[4][4];
    __shared__ float ssd2[16];
    __shared__ float ss0[16];
    __shared__ float srdet;

    const int tid = threadIdx.x;
    const int i = tid >> 4, j = tid & 15;

    sF[i][j] = F[i * 16 + j];
    sQ[i][j] = Q[i * 16 + j];
    if (i < 4) sH[i][j] = H[i * 16 + j];
    if (tid < 16) {
        sR[tid >> 2][tid & 3] = R[tid];
        float v = sd[tid];
        ssd2[tid] = v * v;
    }
    __syncthreads();

    // P = F diag(sd^2) F^T + Q   (covariance after the first predict)
    {
        float acc = sQ[i][j];
#pragma unroll
        for (int k = 0; k < 16; k++) acc = fmaf(sF[i][k] * ssd2[k], sF[j][k], acc);
        sP[i][j] = acc;
    }
    // s0 = F x0
    if (tid < 16) {
        float acc = 0.f;
#pragma unroll
        for (int k = 0; k < 16; k++) acc = fmaf(sF[tid][k], x0[k], acc);
        ss0[tid] = acc;
        g_s0[tid] = acc;
    }
    __syncthreads();
    // y0 = H s0
    if (tid < 4) {
        float acc = 0.f;
#pragma unroll
        for (int k = 0; k < 16; k++) acc = fmaf(sH[tid][k], ss0[k], acc);
        g_y0[tid] = acc;
    }

    float* blob = (float*)g_blob;

#pragma unroll 1
    for (int t = 0; t < NSTEP; ++t) {
        // stage1: HP = H P (64 threads)
        if (tid < 64) {
            int m = tid >> 4, jj = tid & 15;
            float acc = 0.f;
#pragma unroll
            for (int k = 0; k < 16; k++) acc = fmaf(sH[m][k], sP[k][jj], acc);
            sHP[m][jj] = acc;
        }
        __syncthreads();

        // stage2: S = HP H^T + R and 4x4 inverse via cofactors (warp 0, tid<16)
        if (tid < 16) {
            int m = tid >> 2, n = tid & 3;
            float acc = sR[m][n];
#pragma unroll
            for (int k = 0; k < 16; k++) acc = fmaf(sHP[m][k], sH[n][k], acc);
            sS[m][n] = acc;
            __syncwarp(0xffffu);
            // rows/cols excluding m / n: rk = k + (k >= m)
            int r0 = 0 + (0 >= m), r1 = 1 + (1 >= m), r2 = 2 + (2 >= m);
            int c0 = 0 + (0 >= n), c1 = 1 + (1 >= n), c2 = 2 + (2 >= n);
            float a = sS[r0][c0], b = sS[r0][c1], c = sS[r0][c2];
            float d = sS[r1][c0], e = sS[r1][c1], f = sS[r1][c2];
            float g = sS[r2][c0], h = sS[r2][c1], i2 = sS[r2][c2];
            float minor = a * (e * i2 - f * h) - b * (d * i2 - f * g) + c * (d * h - e * g);
            scof[m][n] = ((m + n) & 1) ? -minor : minor;
            __syncwarp(0xffffu);
            if (tid == 0) {
                float det = sS[0][0] * scof[0][0] + sS[0][1] * scof[0][1] +
                            sS[0][2] * scof[0][2] + sS[0][3] * scof[0][3];
                srdet = __fdividef(1.f, det);
            }
            __syncwarp(0xffffu);
            sSi[m][n] = scof[n][m] * srdet;   // Sinv = adj(S)/det
        }
        __syncthreads();

        // stage3: K[i][m] = sum_n HP[n][i] * Sinv[n][m]   (= P H^T S^-1)
        if (tid < 64) {
            int ii = tid >> 2, m = tid & 3;
            float acc = 0.f;
#pragma unroll
            for (int n = 0; n < 4; n++) acc = fmaf(sHP[n][ii], sSi[n][m], acc);
            sK[ii][m] = acc;
        }
        __syncthreads();

        // stage4: L = F K
        if (tid < 64) {
            int ii = tid >> 2, m = tid & 3;
            float acc = 0.f;
#pragma unroll
            for (int k = 0; k < 16; k++) acc = fmaf(sF[ii][k], sK[k][m], acc);
            sL[ii][m] = acc;
        }
        __syncthreads();

        // stage5: A = F - L H (all), LR = L R (threads 64..127)
        {
            float acc = sF[i][j];
#pragma unroll
            for (int m = 0; m < 4; m++) acc = fmaf(-sL[i][m], sH[m][j], acc);
            sA[i][j] = acc;
        }
        if (tid >= 64 && tid < 128) {
            int ii = (tid - 64) >> 2, m = (tid - 64) & 3;
            float acc = 0.f;
#pragma unroll
            for (int n = 0; n < 4; n++) acc = fmaf(sL[ii][n], sR[n][m], acc);
            sLR[ii][m] = acc;
        }
        __syncthreads();

        // stage6: T1 = A P (all); HA = H A (tid<64); HB = H L (tid 64..79)
        {
            float acc = 0.f;
#pragma unroll
            for (int k = 0; k < 16; k++) acc = fmaf(sA[i][k], sP[k][j], acc);
            sT[i][j] = acc;
        }
        if (tid < 64) {
            int m = tid >> 4, jj = tid & 15;
            float acc = 0.f;
#pragma unroll
            for (int k = 0; k < 16; k++) acc = fmaf(sH[m][k], sA[k][jj], acc);
            sHA[m][jj] = acc;
        } else if (tid < 80) {
            int m = (tid - 64) >> 2, n = (tid - 64) & 3;
            float acc = 0.f;
#pragma unroll
            for (int k = 0; k < 16; k++) acc = fmaf(sH[m][k], sL[k][n], acc);
            sHB[m][n] = acc;
        }
        __syncthreads();

        // stage7: P' = T1 A^T + LR L^T + Q ; store blob[t]
        {
            float acc = sQ[i][j];
#pragma unroll
            for (int k = 0; k < 16; k++) acc = fmaf(sT[i][k], sA[j][k], acc);
#pragma unroll
            for (int m = 0; m < 4; m++) acc = fmaf(sLR[i][m], sL[j][m], acc);
            float* base = blob + t * 400;
            base[i * 20 + j] = sA[i][j];
            if (j < 4) base[i * 20 + 16 + j] = sL[i][j];
            if (i < 4) base[(16 + i) * 20 + j] = sHA[i][j];
            if (i < 4 && j < 4) base[(16 + i) * 20 + 16 + j] = sHB[i][j];
            sP[i][j] = acc;   // safe: stage7 reads only sT,sA,sLR,sL,sQ
        }
        __syncthreads();
    }
}

// ---------------------------------------------------------------------------
// Phase 2: per-batch affine recursion. Warp per batch (1024 warps).
// Lane g<16 computes x_new[g]; lanes 16..19 compute/write out[t+1][g-16].
// x broadcast by shfl; obs loaded as a uniform float4 (warp broadcast).
// Distance-3 register prefetch of the 20-float coefficient row.
// ---------------------------------------------------------------------------
#define KF_STEP(Ab, ob, tt)                                                    \
    do {                                                                       \
        float acc0, acc1, res;                                                 \
        acc0 = (Ab)[0].x * __shfl_sync(0xffffffffu, x, 0);                     \
        acc1 = (Ab)[0].y * __shfl_sync(0xffffffffu, x, 1);                     \
        acc0 = fmaf((Ab)[0].z, __shfl_sync(0xffffffffu, x, 2), acc0);          \
        acc1 = fmaf((Ab)[0].w, __shfl_sync(0xffffffffu, x, 3), acc1);          \
        acc0 = fmaf((Ab)[1].x, __shfl_sync(0xffffffffu, x, 4), acc0);          \
        acc1 = fmaf((Ab)[1].y, __shfl_sync(0xffffffffu, x, 5), acc1);          \
        acc0 = fmaf((Ab)[1].z, __shfl_sync(0xffffffffu, x, 6), acc0);          \
        acc1 = fmaf((Ab)[1].w, __shfl_sync(0xffffffffu, x, 7), acc1);          \
        acc0 = fmaf((Ab)[2].x, __shfl_sync(0xffffffffu, x, 8), acc0);          \
        acc1 = fmaf((Ab)[2].y, __shfl_sync(0xffffffffu, x, 9), acc1);          \
        acc0 = fmaf((Ab)[2].z, __shfl_sync(0xffffffffu, x, 10), acc0);         \
        acc1 = fmaf((Ab)[2].w, __shfl_sync(0xffffffffu, x, 11), acc1);         \
        acc0 = fmaf((Ab)[3].x, __shfl_sync(0xffffffffu, x, 12), acc0);         \
        acc1 = fmaf((Ab)[3].y, __shfl_sync(0xffffffffu, x, 13), acc1);         \
        acc0 = fmaf((Ab)[3].z, __shfl_sync(0xffffffffu, x, 14), acc0);         \
        acc1 = fmaf((Ab)[3].w, __shfl_sync(0xffffffffu, x, 15), acc1);         \
        acc0 = fmaf((Ab)[4].x, (ob).x, acc0);                                  \
        acc1 = fmaf((Ab)[4].y, (ob).y, acc1);                                  \
        acc0 = fmaf((Ab)[4].z, (ob).z, acc0);                                  \
        acc1 = fmaf((Ab)[4].w, (ob).w, acc1);                                  \
        res = acc0 + acc1;                                                     \
        if (lane < 16) x = res;                                                \
        else if (lane < 20) op[((tt) + 1) * 4 + (lane - 16)] = res;            \
    } while (0)

__global__ __launch_bounds__(256) void kf_kernel(
    const float* __restrict__ inp, float* __restrict__ out)
{
    const int lane = threadIdx.x & 31;
    const int b = (blockIdx.x << 3) + (threadIdx.x >> 5);
    const int g = (lane < 20) ? lane : 0;

    float x = (lane < 16) ? g_s0[lane] : 0.f;
    float* op = out + b * (NT * NM);
    const float* ip = inp + b * (NT * NM);
    if (lane >= 16 && lane < 20) op[lane - 16] = g_y0[lane - 16];

    const float4* rp = g_blob + g * 5;  // this lane's row; step t at rp + t*100

    float4 A0[5], A1[5], A2[5];
    float4 o0, o1, o2;
#pragma unroll
    for (int c = 0; c < 5; c++) A0[c] = rp[0 * 100 + c];
#pragma unroll
    for (int c = 0; c < 5; c++) A1[c] = rp[1 * 100 + c];
#pragma unroll
    for (int c = 0; c < 5; c++) A2[c] = rp[2 * 100 + c];
    o0 = *(const float4*)(ip + 0 * 4);
    o1 = *(const float4*)(ip + 1 * 4);
    o2 = *(const float4*)(ip + 2 * 4);

#pragma unroll 1
    for (int t = 0; t < NSTEP; t += 3) {
        KF_STEP(A0, o0, t);
        {
            int tp = t + 3; if (tp > NSTEP - 1) tp = NSTEP - 1;
#pragma unroll
            for (int c = 0; c < 5; c++) A0[c] = rp[tp * 100 + c];
            o0 = *(const float4*)(ip + tp * 4);
        }
        KF_STEP(A1, o1, t + 1);
        {
            int tp = t + 4; if (tp > NSTEP - 1) tp = NSTEP - 1;
#pragma unroll
            for (int c = 0; c < 5; c++) A1[c] = rp[tp * 100 + c];
            o1 = *(const float4*)(ip + tp * 4);
        }
        KF_STEP(A2, o2, t + 2);
        {
            int tp = t + 5; if (tp > NSTEP - 1) tp = NSTEP - 1;
#pragma unroll
            for (int c = 0; c < 5; c++) A2[c] = rp[tp * 100 + c];
            o2 = *(const float4*)(ip + tp * 4);
        }
    }
}

extern "C" void kernel_launch(void* const* d_in, const int* in_sizes, int n_in,
                              void* d_out, int out_size) {
    const float* inp = (const float*)d_in[0];
    const float* F   = (const float*)d_in[1];
    const float* H   = (const float*)d_in[2];
    const float* Q   = (const float*)d_in[3];
    const float* R   = (const float*)d_in[4];
    const float* x0  = (const float*)d_in[5];
    const float* sd  = (const float*)d_in[6];
    float* out = (float*)d_out;

    riccati_kernel<<<1, 256>>>(F, H, Q, R, x0, sd);
    kf_kernel<<<128, 256>>>(inp, out);
}

// round 4
// speedup vs baseline: 1.0658x; 1.0658x over previous
#include <cuda_runtime.h>

#define NB 1024
#define NT 256
#define NS 16
#define NM 4
#define NSTEP 255
#define ROWF 20
#define CH 15            // kf chunk: 255 = 17 * 15
#define CHF4 (CH * 100)  // float4 per chunk = 1500

// blob[t]: 20x20 floats. row g<16: [A_t[g][0..15] | L_t[g][0..3]]
//          row 16+m:    [HA_t[m][0..15] | HB_t[m][0..3]]
__device__ float4 g_blob[NSTEP * 100];
__device__ float  g_s0[16];
__device__ float  g_y0[4];

// ---------------------------------------------------------------------------
// Phase 1: R1-verbatim Riccati (Joseph form, proven correct) + NaN-safe
// convergence early-exit. One block of 256 threads; tid -> (i,j) of 16x16.
// ---------------------------------------------------------------------------
__global__ __launch_bounds__(256, 1) void riccati_kernel(
    const float* __restrict__ F, const float* __restrict__ H,
    const float* __restrict__ Q, const float* __restrict__ R,
    const float* __restrict__ x0, const float* __restrict__ sd)
{
    __shared__ float sP[16][ROWF];
    __shared__ float sT[16][ROWF];
    __shared__ float sA[16][ROWF];
    __shared__ float sF[16][ROWF];
    __shared__ float sQ[16][ROWF];
    __shared__ float sH[4][ROWF];
    __shared__ float sHP[4][ROWF];
    __shared__ float sHA[4][ROWF];
    __shared__ __align__(16) float sK[16][4];
    __shared__ __align__(16) float sL[16][4];
    __shared__ __align__(16) float sLR[16][4];
    __shared__ float sS[4][4];
    __shared__ float sSi[4][4];
    __shared__ float sR[4][4];
    __shared__ float sHB[4][4];
    __shared__ float scof[4][4];
    __shared__ float ssd2[16];
    __shared__ float ss0[16];
    __shared__ float srdet;

    const int tid = threadIdx.x;
    const int i = tid >> 4, j = tid & 15;

    sF[i][j] = F[i * 16 + j];
    sQ[i][j] = Q[i * 16 + j];
    if (i < 4) sH[i][j] = H[i * 16 + j];
    if (tid < 16) {
        sR[tid >> 2][tid & 3] = R[tid];
        float v = sd[tid];
        ssd2[tid] = v * v;
    }
    __syncthreads();

    // P = F diag(sd^2) F^T + Q   (covariance after the first predict)
    {
        float acc = sQ[i][j];
#pragma unroll
        for (int k = 0; k < 16; k++) acc = fmaf(sF[i][k] * ssd2[k], sF[j][k], acc);
        sP[i][j] = acc;
    }
    // s0 = F x0
    if (tid < 16) {
        float acc = 0.f;
#pragma unroll
        for (int k = 0; k < 16; k++) acc = fmaf(sF[tid][k], x0[k], acc);
        ss0[tid] = acc;
        g_s0[tid] = acc;
    }
    __syncthreads();
    // y0 = H s0
    if (tid < 4) {
        float acc = 0.f;
#pragma unroll
        for (int k = 0; k < 16; k++) acc = fmaf(sH[tid][k], ss0[k], acc);
        g_y0[tid] = acc;
    }

    float* blob = (float*)g_blob;

#pragma unroll 1
    for (int t = 0; t < NSTEP; ++t) {
        // stage1: HP = H P (64 threads)
        if (tid < 64) {
            int m = tid >> 4, jj = tid & 15;
            float acc = 0.f;
#pragma unroll
            for (int k = 0; k < 16; k++) acc = fmaf(sH[m][k], sP[k][jj], acc);
            sHP[m][jj] = acc;
        }
        __syncthreads();

        // stage2: S = HP H^T + R and 4x4 inverse via cofactors (tid<16)
        if (tid < 16) {
            int m = tid >> 2, n = tid & 3;
            float acc = sR[m][n];
#pragma unroll
            for (int k = 0; k < 16; k++) acc = fmaf(sHP[m][k], sH[n][k], acc);
            sS[m][n] = acc;
            __syncwarp(0xffffu);
            int r0 = 0 + (0 >= m), r1 = 1 + (1 >= m), r2 = 2 + (2 >= m);
            int c0 = 0 + (0 >= n), c1 = 1 + (1 >= n), c2 = 2 + (2 >= n);
            float a = sS[r0][c0], b = sS[r0][c1], c = sS[r0][c2];
            float d = sS[r1][c0], e = sS[r1][c1], f = sS[r1][c2];
            float g = sS[r2][c0], h = sS[r2][c1], i2 = sS[r2][c2];
            float minor = a * (e * i2 - f * h) - b * (d * i2 - f * g) + c * (d * h - e * g);
            scof[m][n] = ((m + n) & 1) ? -minor : minor;
            __syncwarp(0xffffu);
            if (tid == 0) {
                float det = sS[0][0] * scof[0][0] + sS[0][1] * scof[0][1] +
                            sS[0][2] * scof[0][2] + sS[0][3] * scof[0][3];
                srdet = __fdividef(1.f, det);
            }
            __syncwarp(0xffffu);
            sSi[m][n] = scof[n][m] * srdet;   // Sinv = adj(S)/det
        }
        __syncthreads();

        // stage3: K[i][m] = sum_n HP[n][i] * Sinv[n][m]   (= P H^T S^-1)
        if (tid < 64) {
            int ii = tid >> 2, m = tid & 3;
            float acc = 0.f;
#pragma unroll
            for (int n = 0; n < 4; n++) acc = fmaf(sHP[n][ii], sSi[n][m], acc);
            sK[ii][m] = acc;
        }
        __syncthreads();

        // stage4: L = F K
        if (tid < 64) {
            int ii = tid >> 2, m = tid & 3;
            float acc = 0.f;
#pragma unroll
            for (int k = 0; k < 16; k++) acc = fmaf(sF[ii][k], sK[k][m], acc);
            sL[ii][m] = acc;
        }
        __syncthreads();

        // stage5: A = F - L H (all), LR = L R (threads 64..127)
        {
            float acc = sF[i][j];
#pragma unroll
            for (int m = 0; m < 4; m++) acc = fmaf(-sL[i][m], sH[m][j], acc);
            sA[i][j] = acc;
        }
        if (tid >= 64 && tid < 128) {
            int ii = (tid - 64) >> 2, m = (tid - 64) & 3;
            float acc = 0.f;
#pragma unroll
            for (int n = 0; n < 4; n++) acc = fmaf(sL[ii][n], sR[n][m], acc);
            sLR[ii][m] = acc;
        }
        __syncthreads();

        // stage6: T1 = A P (all); HA = H A (tid<64); HB = H L (tid 64..79)
        {
            float acc = 0.f;
#pragma unroll
            for (int k = 0; k < 16; k++) acc = fmaf(sA[i][k], sP[k][j], acc);
            sT[i][j] = acc;
        }
        if (tid < 64) {
            int m = tid >> 4, jj = tid & 15;
            float acc = 0.f;
#pragma unroll
            for (int k = 0; k < 16; k++) acc = fmaf(sH[m][k], sA[k][jj], acc);
            sHA[m][jj] = acc;
        } else if (tid < 80) {
            int m = (tid - 64) >> 2, n = (tid - 64) & 3;
            float acc = 0.f;
#pragma unroll
            for (int k = 0; k < 16; k++) acc = fmaf(sH[m][k], sL[k][n], acc);
            sHB[m][n] = acc;
        }
        __syncthreads();

        // stage7: P' = T1 A^T + LR L^T + Q ; store blob[t] ; convergence flag
        int flag;
        {
            float acc = sQ[i][j];
#pragma unroll
            for (int k = 0; k < 16; k++) acc = fmaf(sT[i][k], sA[j][k], acc);
#pragma unroll
            for (int m = 0; m < 4; m++) acc = fmaf(sLR[i][m], sL[j][m], acc);
            float* base = blob + t * 400;
            base[i * 20 + j] = sA[i][j];
            if (j < 4) base[i * 20 + 16 + j] = sL[i][j];
            if (i < 4) base[(16 + i) * 20 + j] = sHA[i][j];
            if (i < 4 && j < 4) base[(16 + i) * 20 + 16 + j] = sHB[i][j];
            float oldp = sP[i][j];
            // NaN-safe: NaN compares false vs <=, so flag=1 (NOT converged)
            flag = !(fabsf(acc - oldp) <= 1e-6f * (fabsf(acc) + 1e-3f));
            sP[i][j] = acc;   // safe: stage7 reads only sT,sA,sLR,sL,sQ
        }
        if (!__syncthreads_or(flag)) {
            // converged: replicate the fixed-point map for all remaining steps
            for (int t2 = t + 1; t2 < NSTEP; ++t2) {
                float* b2 = blob + t2 * 400;
                b2[i * 20 + j] = sA[i][j];
                if (j < 4) b2[i * 20 + 16 + j] = sL[i][j];
                if (i < 4) b2[(16 + i) * 20 + j] = sHA[i][j];
                if (i < 4 && j < 4) b2[(16 + i) * 20 + 16 + j] = sHB[i][j];
            }
            break;
        }
    }
}

// ---------------------------------------------------------------------------
// Phase 2: warp-per-batch affine recursion; blob staged through shared via a
// compiler-visible LDG->reg->STS double-buffer. One barrier per 15-step
// chunk; chunk c+2 prefetched into registers while chunk c runs.
// ---------------------------------------------------------------------------
#define KF_STEP(Ab, ob, tt)                                                    \
    do {                                                                       \
        float acc0, acc1, res;                                                 \
        acc0 = (Ab)[0].x * __shfl_sync(0xffffffffu, x, 0);                     \
        acc1 = (Ab)[0].y * __shfl_sync(0xffffffffu, x, 1);                     \
        acc0 = fmaf((Ab)[0].z, __shfl_sync(0xffffffffu, x, 2), acc0);          \
        acc1 = fmaf((Ab)[0].w, __shfl_sync(0xffffffffu, x, 3), acc1);          \
        acc0 = fmaf((Ab)[1].x, __shfl_sync(0xffffffffu, x, 4), acc0);          \
        acc1 = fmaf((Ab)[1].y, __shfl_sync(0xffffffffu, x, 5), acc1);          \
        acc0 = fmaf((Ab)[1].z, __shfl_sync(0xffffffffu, x, 6), acc0);          \
        acc1 = fmaf((Ab)[1].w, __shfl_sync(0xffffffffu, x, 7), acc1);          \
        acc0 = fmaf((Ab)[2].x, __shfl_sync(0xffffffffu, x, 8), acc0);          \
        acc1 = fmaf((Ab)[2].y, __shfl_sync(0xffffffffu, x, 9), acc1);          \
        acc0 = fmaf((Ab)[2].z, __shfl_sync(0xffffffffu, x, 10), acc0);         \
        acc1 = fmaf((Ab)[2].w, __shfl_sync(0xffffffffu, x, 11), acc1);         \
        acc0 = fmaf((Ab)[3].x, __shfl_sync(0xffffffffu, x, 12), acc0);         \
        acc1 = fmaf((Ab)[3].y, __shfl_sync(0xffffffffu, x, 13), acc1);         \
        acc0 = fmaf((Ab)[3].z, __shfl_sync(0xffffffffu, x, 14), acc0);         \
        acc1 = fmaf((Ab)[3].w, __shfl_sync(0xffffffffu, x, 15), acc1);         \
        acc0 = fmaf((Ab)[4].x, (ob).x, acc0);                                  \
        acc1 = fmaf((Ab)[4].y, (ob).y, acc1);                                  \
        acc0 = fmaf((Ab)[4].z, (ob).z, acc0);                                  \
        acc1 = fmaf((Ab)[4].w, (ob).w, acc1);                                  \
        res = acc0 + acc1;                                                     \
        if (lane < 16) x = res;                                                \
        else if (lane < 20) op[((tt) + 1) * 4 + (lane - 16)] = res;            \
    } while (0)

__global__ __launch_bounds__(256) void kf_kernel(
    const float* __restrict__ inp, float* __restrict__ out)
{
    __shared__ __align__(16) float4 sblob[2][CHF4];  // 2 x 24000 B

    const int tid = threadIdx.x;
    const int lane = tid & 31;
    const int b = (blockIdx.x << 3) + (tid >> 5);
    const int g = (lane < 20) ? lane : 0;

    float x = (lane < 16) ? g_s0[lane] : 0.f;
    float* op = out + b * (NT * NM);
    const float* ip = inp + b * (NT * NM);
    if (lane >= 16 && lane < 20) op[lane - 16] = g_y0[lane - 16];

    const float4* gb = g_blob;
    float4 Rg[6];

    // prologue: chunk0 -> regs -> buf0 ; chunk1 -> regs (held)
#pragma unroll
    for (int r = 0; r < 6; r++) {
        int idx = tid + r * 256;
        if (idx < CHF4) Rg[r] = gb[idx];
    }
#pragma unroll
    for (int r = 0; r < 6; r++) {
        int idx = tid + r * 256;
        if (idx < CHF4) sblob[0][idx] = Rg[r];
    }
#pragma unroll
    for (int r = 0; r < 6; r++) {
        int idx = tid + r * 256;
        if (idx < CHF4) Rg[r] = gb[CHF4 + idx];
    }
    __syncthreads();  // buf0 visible (BAR drains STS)

    int t = 0;
    float4 obn = *(const float4*)(ip);

#pragma unroll 1
    for (int c = 0; c < 17; ++c) {
        const float* sb = (const float*)sblob[c & 1];
#pragma unroll 1
        for (int s = 0; s < CH; ++s, ++t) {
            const float4* rp4 = (const float4*)(sb + s * 400 + g * 20);
            float4 A[5];
            A[0] = rp4[0]; A[1] = rp4[1]; A[2] = rp4[2]; A[3] = rp4[3]; A[4] = rp4[4];
            float4 ob = obn;
            int tn = (t + 1 < NSTEP) ? t + 1 : t;
            obn = *(const float4*)(ip + tn * 4);
            KF_STEP(A, ob, t);
        }
        if (c < 16) {
            // store held chunk c+1 into the buffer not being read this iter
            float4* dst = sblob[(c + 1) & 1];
#pragma unroll
            for (int r = 0; r < 6; r++) {
                int idx = tid + r * 256;
                if (idx < CHF4) dst[idx] = Rg[r];
            }
            if (c + 2 < 17) {
#pragma unroll
                for (int r = 0; r < 6; r++) {
                    int idx = tid + r * 256;
                    if (idx < CHF4) Rg[r] = gb[(c + 2) * CHF4 + idx];
                }
            }
        }
        __syncthreads();  // readers of buf c&1 done; buf (c+1)&1 published
    }
}

extern "C" void kernel_launch(void* const* d_in, const int* in_sizes, int n_in,
                              void* d_out, int out_size) {
    const float* inp = (const float*)d_in[0];
    const float* F   = (const float*)d_in[1];
    const float* H   = (const float*)d_in[2];
    const float* Q   = (const float*)d_in[3];
    const float* R   = (const float*)d_in[4];
    const float* x0  = (const float*)d_in[5];
    const float* sd  = (const float*)d_in[6];
    float* out = (float*)d_out;

    riccati_kernel<<<1, 256>>>(F, H, Q, R, x0, sd);
    kf_kernel<<<128, 256>>>(inp, out);
}

// round 5
// speedup vs baseline: 1.4362x; 1.3476x over previous
#include <cuda_runtime.h>

#define NB 1024
#define NT 256
#define NS 16
#define NM 4
#define NSTEP 255
#define ROWF 20
#define CH 15            // kf chunk: 255 = 17 * 15
#define CHF4 (CH * 100)  // float4 per chunk = 1500

// blob[t]: 20x20 floats. row g<16: [A_t[g][0..15] | L_t[g][0..3]]
//          row 16+m:    [HA_t[m][0..15] | HB_t[m][0..3]]
__device__ float4 g_blob[NSTEP * 100];
__device__ float  g_s0[16];
__device__ float  g_y0[4];

// ---------------------------------------------------------------------------
// Phase 1: Joseph-form Riccati (R1-proven math), 6 barriers/step:
//   stage1: HP = H P
//   stage2: warp0: S = HP H^T + R, S^-1 (cofactors)  ||  thr64..127: FHP = F (HP)^T
//   stage3: L = FHP S^-1         ( == F P H^T S^-1 = F K, P symmetric )
//   stage5: A = F - L H ; LR = L R
//   stage6: T1 = A P ; HA = H A ; HB = H L
//   stage7: P' = T1 A^T + LR L^T + Q ; store blob ; convergence check
// NaN-safe convergence early-exit with threshold above fp32 jitter floor.
// ---------------------------------------------------------------------------
__global__ __launch_bounds__(256, 1) void riccati_kernel(
    const float* __restrict__ F, const float* __restrict__ H,
    const float* __restrict__ Q, const float* __restrict__ R,
    const float* __restrict__ x0, const float* __restrict__ sd)
{
    __shared__ float sP[16][ROWF];
    __shared__ float sT[16][ROWF];
    __shared__ float sA[16][ROWF];
    __shared__ float sF[16][ROWF];
    __shared__ float sQ[16][ROWF];
    __shared__ float sH[4][ROWF];
    __shared__ float sHP[4][ROWF];
    __shared__ float sHA[4][ROWF];
    __shared__ __align__(16) float sFHP[16][4];
    __shared__ __align__(16) float sL[16][4];
    __shared__ __align__(16) float sLR[16][4];
    __shared__ float sS[4][4];
    __shared__ float sSi[4][4];
    __shared__ float sR[4][4];
    __shared__ float sHB[4][4];
    __shared__ float scof[4][4];
    __shared__ float ssd2[16];
    __shared__ float ss0[16];
    __shared__ float srdet;

    const int tid = threadIdx.x;
    const int i = tid >> 4, j = tid & 15;

    sF[i][j] = F[i * 16 + j];
    sQ[i][j] = Q[i * 16 + j];
    if (i < 4) sH[i][j] = H[i * 16 + j];
    if (tid < 16) {
        sR[tid >> 2][tid & 3] = R[tid];
        float v = sd[tid];
        ssd2[tid] = v * v;
    }
    __syncthreads();

    // P = F diag(sd^2) F^T + Q   (covariance after the first predict)
    {
        float a0 = sQ[i][j], a1 = 0.f, a2 = 0.f, a3 = 0.f;
#pragma unroll
        for (int k = 0; k < 16; k += 4) {
            a0 = fmaf(sF[i][k + 0] * ssd2[k + 0], sF[j][k + 0], a0);
            a1 = fmaf(sF[i][k + 1] * ssd2[k + 1], sF[j][k + 1], a1);
            a2 = fmaf(sF[i][k + 2] * ssd2[k + 2], sF[j][k + 2], a2);
            a3 = fmaf(sF[i][k + 3] * ssd2[k + 3], sF[j][k + 3], a3);
        }
        sP[i][j] = (a0 + a1) + (a2 + a3);
    }
    // s0 = F x0
    if (tid < 16) {
        float acc = 0.f;
#pragma unroll
        for (int k = 0; k < 16; k++) acc = fmaf(sF[tid][k], x0[k], acc);
        ss0[tid] = acc;
        g_s0[tid] = acc;
    }
    __syncthreads();
    // y0 = H s0
    if (tid < 4) {
        float acc = 0.f;
#pragma unroll
        for (int k = 0; k < 16; k++) acc = fmaf(sH[tid][k], ss0[k], acc);
        g_y0[tid] = acc;
    }

    float* blob = (float*)g_blob;

#pragma unroll 1
    for (int t = 0; t < NSTEP; ++t) {
        // stage1: HP = H P (64 threads)
        if (tid < 64) {
            int m = tid >> 4, jj = tid & 15;
            float a0 = 0.f, a1 = 0.f, a2 = 0.f, a3 = 0.f;
#pragma unroll
            for (int k = 0; k < 16; k += 4) {
                a0 = fmaf(sH[m][k + 0], sP[k + 0][jj], a0);
                a1 = fmaf(sH[m][k + 1], sP[k + 1][jj], a1);
                a2 = fmaf(sH[m][k + 2], sP[k + 2][jj], a2);
                a3 = fmaf(sH[m][k + 3], sP[k + 3][jj], a3);
            }
            sHP[m][jj] = (a0 + a1) + (a2 + a3);
        }
        __syncthreads();

        // stage2: warp0 (tid<16): S = HP H^T + R and 4x4 cofactor inverse.
        //         threads 64..127: FHP[i][n] = sum_k F[i][k] * HP[n][k]
        if (tid < 16) {
            int m = tid >> 2, n = tid & 3;
            float acc = sR[m][n];
#pragma unroll
            for (int k = 0; k < 16; k++) acc = fmaf(sHP[m][k], sH[n][k], acc);
            sS[m][n] = acc;
            __syncwarp(0xffffu);
            int r0 = 0 + (0 >= m), r1 = 1 + (1 >= m), r2 = 2 + (2 >= m);
            int c0 = 0 + (0 >= n), c1 = 1 + (1 >= n), c2 = 2 + (2 >= n);
            float a = sS[r0][c0], b = sS[r0][c1], c = sS[r0][c2];
            float d = sS[r1][c0], e = sS[r1][c1], f = sS[r1][c2];
            float g = sS[r2][c0], h = sS[r2][c1], i2 = sS[r2][c2];
            float minor = a * (e * i2 - f * h) - b * (d * i2 - f * g) + c * (d * h - e * g);
            scof[m][n] = ((m + n) & 1) ? -minor : minor;
            __syncwarp(0xffffu);
            if (tid == 0) {
                float det = sS[0][0] * scof[0][0] + sS[0][1] * scof[0][1] +
                            sS[0][2] * scof[0][2] + sS[0][3] * scof[0][3];
                srdet = __fdividef(1.f, det);
            }
            __syncwarp(0xffffu);
            sSi[m][n] = scof[n][m] * srdet;   // Sinv = adj(S)/det
        }
        if (tid >= 64 && tid < 128) {
            int ii = (tid - 64) >> 2, n = (tid - 64) & 3;
            float a0 = 0.f, a1 = 0.f, a2 = 0.f, a3 = 0.f;
#pragma unroll
            for (int k = 0; k < 16; k += 4) {
                a0 = fmaf(sF[ii][k + 0], sHP[n][k + 0], a0);
                a1 = fmaf(sF[ii][k + 1], sHP[n][k + 1], a1);
                a2 = fmaf(sF[ii][k + 2], sHP[n][k + 2], a2);
                a3 = fmaf(sF[ii][k + 3], sHP[n][k + 3], a3);
            }
            sFHP[ii][n] = (a0 + a1) + (a2 + a3);
        }
        __syncthreads();

        // stage3: L[i][m] = sum_n FHP[i][n] * Sinv[n][m]   ( = F K )
        if (tid < 64) {
            int ii = tid >> 2, m = tid & 3;
            float acc = 0.f;
#pragma unroll
            for (int n = 0; n < 4; n++) acc = fmaf(sFHP[ii][n], sSi[n][m], acc);
            sL[ii][m] = acc;
        }
        __syncthreads();

        // stage5: A = F - L H (all), LR = L R (threads 64..127)
        {
            float acc = sF[i][j];
#pragma unroll
            for (int m = 0; m < 4; m++) acc = fmaf(-sL[i][m], sH[m][j], acc);
            sA[i][j] = acc;
        }
        if (tid >= 64 && tid < 128) {
            int ii = (tid - 64) >> 2, m = (tid - 64) & 3;
            float acc = 0.f;
#pragma unroll
            for (int n = 0; n < 4; n++) acc = fmaf(sL[ii][n], sR[n][m], acc);
            sLR[ii][m] = acc;
        }
        __syncthreads();

        // stage6: T1 = A P (all); HA = H A (tid<64); HB = H L (tid 64..79)
        {
            float a0 = 0.f, a1 = 0.f, a2 = 0.f, a3 = 0.f;
#pragma unroll
            for (int k = 0; k < 16; k += 4) {
                a0 = fmaf(sA[i][k + 0], sP[k + 0][j], a0);
                a1 = fmaf(sA[i][k + 1], sP[k + 1][j], a1);
                a2 = fmaf(sA[i][k + 2], sP[k + 2][j], a2);
                a3 = fmaf(sA[i][k + 3], sP[k + 3][j], a3);
            }
            sT[i][j] = (a0 + a1) + (a2 + a3);
        }
        if (tid < 64) {
            int m = tid >> 4, jj = tid & 15;
            float acc = 0.f;
#pragma unroll
            for (int k = 0; k < 16; k++) acc = fmaf(sH[m][k], sA[k][jj], acc);
            sHA[m][jj] = acc;
        } else if (tid < 80) {
            int m = (tid - 64) >> 2, n = (tid - 64) & 3;
            float acc = 0.f;
#pragma unroll
            for (int k = 0; k < 16; k++) acc = fmaf(sH[m][k], sL[k][n], acc);
            sHB[m][n] = acc;
        }
        __syncthreads();

        // stage7: P' = T1 A^T + LR L^T + Q ; store blob[t] ; convergence flag
        int flag;
        {
            float a0 = sQ[i][j], a1 = 0.f, a2 = 0.f, a3 = 0.f;
#pragma unroll
            for (int k = 0; k < 16; k += 4) {
                a0 = fmaf(sT[i][k + 0], sA[j][k + 0], a0);
                a1 = fmaf(sT[i][k + 1], sA[j][k + 1], a1);
                a2 = fmaf(sT[i][k + 2], sA[j][k + 2], a2);
                a3 = fmaf(sT[i][k + 3], sA[j][k + 3], a3);
            }
            float acc = (a0 + a1) + (a2 + a3);
#pragma unroll
            for (int m = 0; m < 4; m++) acc = fmaf(sLR[i][m], sL[j][m], acc);
            float* base = blob + t * 400;
            base[i * 20 + j] = sA[i][j];
            if (j < 4) base[i * 20 + 16 + j] = sL[i][j];
            if (i < 4) base[(16 + i) * 20 + j] = sHA[i][j];
            if (i < 4 && j < 4) base[(16 + i) * 20 + 16 + j] = sHB[i][j];
            float oldp = sP[i][j];
            // NaN-safe (NaN -> flag=1); threshold above fp32 jitter floor.
            flag = !(fabsf(acc - oldp) <= 1e-5f * fabsf(acc) + 1e-6f);
            sP[i][j] = acc;   // safe: stage7 reads only sT,sA,sLR,sL,sQ
        }
        if (!__syncthreads_or(flag)) {
            // converged: replicate the fixed-point map for all remaining steps
            for (int t2 = t + 1; t2 < NSTEP; ++t2) {
                float* b2 = blob + t2 * 400;
                b2[i * 20 + j] = sA[i][j];
                if (j < 4) b2[i * 20 + 16 + j] = sL[i][j];
                if (i < 4) b2[(16 + i) * 20 + j] = sHA[i][j];
                if (i < 4 && j < 4) b2[(16 + i) * 20 + 16 + j] = sHB[i][j];
            }
            break;
        }
    }
}

// ---------------------------------------------------------------------------
// Phase 2: warp-per-batch affine recursion; blob staged through shared via a
// compiler-visible LDG->reg->STS double-buffer. One barrier per 15-step
// chunk; chunk c+2 prefetched into registers while chunk c runs.
// ---------------------------------------------------------------------------
#define KF_STEP(Ab, ob, tt)                                                    \
    do {                                                                       \
        float acc0, acc1, res;                                                 \
        acc0 = (Ab)[0].x * __shfl_sync(0xffffffffu, x, 0);                     \
        acc1 = (Ab)[0].y * __shfl_sync(0xffffffffu, x, 1);                     \
        acc0 = fmaf((Ab)[0].z, __shfl_sync(0xffffffffu, x, 2), acc0);          \
        acc1 = fmaf((Ab)[0].w, __shfl_sync(0xffffffffu, x, 3), acc1);          \
        acc0 = fmaf((Ab)[1].x, __shfl_sync(0xffffffffu, x, 4), acc0);          \
        acc1 = fmaf((Ab)[1].y, __shfl_sync(0xffffffffu, x, 5), acc1);          \
        acc0 = fmaf((Ab)[1].z, __shfl_sync(0xffffffffu, x, 6), acc0);          \
        acc1 = fmaf((Ab)[1].w, __shfl_sync(0xffffffffu, x, 7), acc1);          \
        acc0 = fmaf((Ab)[2].x, __shfl_sync(0xffffffffu, x, 8), acc0);          \
        acc1 = fmaf((Ab)[2].y, __shfl_sync(0xffffffffu, x, 9), acc1);          \
        acc0 = fmaf((Ab)[2].z, __shfl_sync(0xffffffffu, x, 10), acc0);         \
        acc1 = fmaf((Ab)[2].w, __shfl_sync(0xffffffffu, x, 11), acc1);         \
        acc0 = fmaf((Ab)[3].x, __shfl_sync(0xffffffffu, x, 12), acc0);         \
        acc1 = fmaf((Ab)[3].y, __shfl_sync(0xffffffffu, x, 13), acc1);         \
        acc0 = fmaf((Ab)[3].z, __shfl_sync(0xffffffffu, x, 14), acc0);         \
        acc1 = fmaf((Ab)[3].w, __shfl_sync(0xffffffffu, x, 15), acc1);         \
        acc0 = fmaf((Ab)[4].x, (ob).x, acc0);                                  \
        acc1 = fmaf((Ab)[4].y, (ob).y, acc1);                                  \
        acc0 = fmaf((Ab)[4].z, (ob).z, acc0);                                  \
        acc1 = fmaf((Ab)[4].w, (ob).w, acc1);                                  \
        res = acc0 + acc1;                                                     \
        if (lane < 16) x = res;                                                \
        else if (lane < 20) op[((tt) + 1) * 4 + (lane - 16)] = res;            \
    } while (0)

__global__ __launch_bounds__(256) void kf_kernel(
    const float* __restrict__ inp, float* __restrict__ out)
{
    __shared__ __align__(16) float4 sblob[2][CHF4];  // 2 x 24000 B

    const int tid = threadIdx.x;
    const int lane = tid & 31;
    const int b = (blockIdx.x << 3) + (tid >> 5);
    const int g = (lane < 20) ? lane : 0;

    float x = (lane < 16) ? g_s0[lane] : 0.f;
    float* op = out + b * (NT * NM);
    const float* ip = inp + b * (NT * NM);
    if (lane >= 16 && lane < 20) op[lane - 16] = g_y0[lane - 16];

    const float4* gb = g_blob;
    float4 Rg[6];

    // prologue: chunk0 -> regs -> buf0 ; chunk1 -> regs (held)
#pragma unroll
    for (int r = 0; r < 6; r++) {
        int idx = tid + r * 256;
        if (idx < CHF4) Rg[r] = gb[idx];
    }
#pragma unroll
    for (int r = 0; r < 6; r++) {
        int idx = tid + r * 256;
        if (idx < CHF4) sblob[0][idx] = Rg[r];
    }
#pragma unroll
    for (int r = 0; r < 6; r++) {
        int idx = tid + r * 256;
        if (idx < CHF4) Rg[r] = gb[CHF4 + idx];
    }
    __syncthreads();  // buf0 visible (BAR drains STS)

    int t = 0;
    float4 obn = *(const float4*)(ip);

#pragma unroll 1
    for (int c = 0; c < 17; ++c) {
        const float* sb = (const float*)sblob[c & 1];
#pragma unroll 1
        for (int s = 0; s < CH; ++s, ++t) {
            const float4* rp4 = (const float4*)(sb + s * 400 + g * 20);
            float4 A[5];
            A[0] = rp4[0]; A[1] = rp4[1]; A[2] = rp4[2]; A[3] = rp4[3]; A[4] = rp4[4];
            float4 ob = obn;
            int tn = (t + 1 < NSTEP) ? t + 1 : t;
            obn = *(const float4*)(ip + tn * 4);
            KF_STEP(A, ob, t);
        }
        if (c < 16) {
            // store held chunk c+1 into the buffer not being read this iter
            float4* dst = sblob[(c + 1) & 1];
#pragma unroll
            for (int r = 0; r < 6; r++) {
                int idx = tid + r * 256;
                if (idx < CHF4) dst[idx] = Rg[r];
            }
            if (c + 2 < 17) {
#pragma unroll
                for (int r = 0; r < 6; r++) {
                    int idx = tid + r * 256;
                    if (idx < CHF4) Rg[r] = gb[(c + 2) * CHF4 + idx];
                }
            }
        }
        __syncthreads();  // readers of buf c&1 done; buf (c+1)&1 published
    }
}

extern "C" void kernel_launch(void* const* d_in, const int* in_sizes, int n_in,
                              void* d_out, int out_size) {
    const float* inp = (const float*)d_in[0];
    const float* F   = (const float*)d_in[1];
    const float* H   = (const float*)d_in[2];
    const float* Q   = (const float*)d_in[3];
    const float* R   = (const float*)d_in[4];
    const float* x0  = (const float*)d_in[5];
    const float* sd  = (const float*)d_in[6];
    float* out = (float*)d_out;

    riccati_kernel<<<1, 256>>>(F, H, Q, R, x0, sd);
    kf_kernel<<<128, 256>>>(inp, out);
}

// round 6
// speedup vs baseline: 1.5715x; 1.0942x over previous
#include <cuda_runtime.h>

#define NB 1024
#define NT 256
#define NS 16
#define NM 4
#define NSTEP 255
#define ROWF 20
#define CH 15            // chunk: 255 = 17 * 15
#define NCHUNK 17
#define CHF4 (CH * 100)  // float4 per chunk = 1500

// blob[t]: 100 float4 per step, float4-column-major:
//   f4 index (c*20 + row): row<16 state rows [A|L], row 16+m = [HA|HB] rows.
//   Column block c<4 covers matrix cols 4c..4c+3; c==4 covers cols 16..19 (L/HB).
__device__ float4 g_blob[NSTEP * 100];
__device__ float  g_s0[16];
__device__ float  g_y0[4];
__device__ int    g_ready;   // chunks published (monotonic within a launch)

__global__ void reset_kernel() { g_ready = 0; }

// ---------------------------------------------------------------------------
// KF consumer step: lanes 0..15 new state, lanes 16..19 write output.
// ---------------------------------------------------------------------------
#define KF_STEP(Ab, ob, tt)                                                    \
    do {                                                                       \
        float acc0, acc1, res;                                                 \
        acc0 = (Ab)[0].x * __shfl_sync(0xffffffffu, x, 0);                     \
        acc1 = (Ab)[0].y * __shfl_sync(0xffffffffu, x, 1);                     \
        acc0 = fmaf((Ab)[0].z, __shfl_sync(0xffffffffu, x, 2), acc0);          \
        acc1 = fmaf((Ab)[0].w, __shfl_sync(0xffffffffu, x, 3), acc1);          \
        acc0 = fmaf((Ab)[1].x, __shfl_sync(0xffffffffu, x, 4), acc0);          \
        acc1 = fmaf((Ab)[1].y, __shfl_sync(0xffffffffu, x, 5), acc1);          \
        acc0 = fmaf((Ab)[1].z, __shfl_sync(0xffffffffu, x, 6), acc0);          \
        acc1 = fmaf((Ab)[1].w, __shfl_sync(0xffffffffu, x, 7), acc1);          \
        acc0 = fmaf((Ab)[2].x, __shfl_sync(0xffffffffu, x, 8), acc0);          \
        acc1 = fmaf((Ab)[2].y, __shfl_sync(0xffffffffu, x, 9), acc1);          \
        acc0 = fmaf((Ab)[2].z, __shfl_sync(0xffffffffu, x, 10), acc0);         \
        acc1 = fmaf((Ab)[2].w, __shfl_sync(0xffffffffu, x, 11), acc1);         \
        acc0 = fmaf((Ab)[3].x, __shfl_sync(0xffffffffu, x, 12), acc0);         \
        acc1 = fmaf((Ab)[3].y, __shfl_sync(0xffffffffu, x, 13), acc1);         \
        acc0 = fmaf((Ab)[3].z, __shfl_sync(0xffffffffu, x, 14), acc0);         \
        acc1 = fmaf((Ab)[3].w, __shfl_sync(0xffffffffu, x, 15), acc1);         \
        acc0 = fmaf((Ab)[4].x, (ob).x, acc0);                                  \
        acc1 = fmaf((Ab)[4].y, (ob).y, acc1);                                  \
        acc0 = fmaf((Ab)[4].z, (ob).z, acc0);                                  \
        acc1 = fmaf((Ab)[4].w, (ob).w, acc1);                                  \
        res = acc0 + acc1;                                                     \
        if (lane < 16) x = res;                                                \
        else if (lane < 20) op[((tt) + 1) * 4 + (lane - 16)] = res;            \
    } while (0)

__global__ __launch_bounds__(256, 1) void fused_kernel(
    const float* __restrict__ inp, float* __restrict__ out,
    const float* __restrict__ F, const float* __restrict__ H,
    const float* __restrict__ Q, const float* __restrict__ R,
    const float* __restrict__ x0, const float* __restrict__ sd)
{
    // producer shared state
    __shared__ float sP[16][ROWF];
    __shared__ float sT[16][ROWF];
    __shared__ float sA[16][ROWF];
    __shared__ float sF[16][ROWF];
    __shared__ float sQ[16][ROWF];
    __shared__ float sH[4][ROWF];
    __shared__ float sHP[4][ROWF];
    __shared__ float sHA[4][ROWF];
    __shared__ float sSiH[4][ROWF];
    __shared__ __align__(16) float sFHP[16][4];
    __shared__ __align__(16) float sL[16][4];
    __shared__ __align__(16) float sLR[16][4];
    __shared__ float sS[4][4], sSi[4][4], scof[4][4], sR[4][4], sHB[4][4], sSiR[4][4];
    __shared__ float ssd2[16], ss0[16], srdet;
    // consumer staging buffer
    __shared__ __align__(16) float4 sbuf[CHF4];   // 24 KB

    const int tid = threadIdx.x;

    if (blockIdx.x == 0) {
        // ================= PRODUCER: Riccati (Joseph form, 5 barriers) ======
        const int i = tid >> 4, j = tid & 15;

        sF[i][j] = F[i * 16 + j];
        sQ[i][j] = Q[i * 16 + j];
        if (i < 4) sH[i][j] = H[i * 16 + j];
        if (tid < 16) {
            sR[tid >> 2][tid & 3] = R[tid];
            float v = sd[tid];
            ssd2[tid] = v * v;
        }
        __syncthreads();

        // P = F diag(sd^2) F^T + Q ; s0 = F x0 ; y0 = H s0
        {
            float a0 = sQ[i][j], a1 = 0.f, a2 = 0.f, a3 = 0.f;
#pragma unroll
            for (int k = 0; k < 16; k += 4) {
                a0 = fmaf(sF[i][k + 0] * ssd2[k + 0], sF[j][k + 0], a0);
                a1 = fmaf(sF[i][k + 1] * ssd2[k + 1], sF[j][k + 1], a1);
                a2 = fmaf(sF[i][k + 2] * ssd2[k + 2], sF[j][k + 2], a2);
                a3 = fmaf(sF[i][k + 3] * ssd2[k + 3], sF[j][k + 3], a3);
            }
            sP[i][j] = (a0 + a1) + (a2 + a3);
        }
        if (tid < 16) {
            float acc = 0.f;
#pragma unroll
            for (int k = 0; k < 16; k++) acc = fmaf(sF[tid][k], x0[k], acc);
            ss0[tid] = acc;
            g_s0[tid] = acc;
        }
        __syncthreads();
        if (tid < 4) {
            float acc = 0.f;
#pragma unroll
            for (int k = 0; k < 16; k++) acc = fmaf(sH[tid][k], ss0[k], acc);
            g_y0[tid] = acc;
        }

        float* blob = (float*)g_blob;

#pragma unroll 1
        for (int t = 0; t < NSTEP; ++t) {
            // stage1: HP = H P (64 threads)
            if (tid < 64) {
                int m = tid >> 4, jj = tid & 15;
                float a0 = 0.f, a1 = 0.f, a2 = 0.f, a3 = 0.f;
#pragma unroll
                for (int k = 0; k < 16; k += 4) {
                    a0 = fmaf(sH[m][k + 0], sP[k + 0][jj], a0);
                    a1 = fmaf(sH[m][k + 1], sP[k + 1][jj], a1);
                    a2 = fmaf(sH[m][k + 2], sP[k + 2][jj], a2);
                    a3 = fmaf(sH[m][k + 3], sP[k + 3][jj], a3);
                }
                sHP[m][jj] = (a0 + a1) + (a2 + a3);
            }
            __syncthreads();

            // stage2: warp0: S, Sinv, SiH, SiR   ||  thr64..127: FHP = F (HP)^T
            if (tid < 16) {
                int m = tid >> 2, n = tid & 3;
                float c0 = sR[m][n], c1 = 0.f;
#pragma unroll
                for (int k = 0; k < 16; k += 2) {
                    c0 = fmaf(sHP[m][k], sH[n][k], c0);
                    c1 = fmaf(sHP[m][k + 1], sH[n][k + 1], c1);
                }
                sS[m][n] = c0 + c1;
                __syncwarp(0xffffu);
                int r0 = 0 + (0 >= m), r1 = 1 + (1 >= m), r2 = 2 + (2 >= m);
                int cc0 = 0 + (0 >= n), cc1 = 1 + (1 >= n), cc2 = 2 + (2 >= n);
                float a = sS[r0][cc0], b = sS[r0][cc1], c = sS[r0][cc2];
                float d = sS[r1][cc0], e = sS[r1][cc1], f = sS[r1][cc2];
                float g = sS[r2][cc0], h = sS[r2][cc1], i2 = sS[r2][cc2];
                float minor = a * (e * i2 - f * h) - b * (d * i2 - f * g) + c * (d * h - e * g);
                scof[m][n] = ((m + n) & 1) ? -minor : minor;
                __syncwarp(0xffffu);
                if (tid == 0) {
                    float det = sS[0][0] * scof[0][0] + sS[0][1] * scof[0][1] +
                                sS[0][2] * scof[0][2] + sS[0][3] * scof[0][3];
                    srdet = __fdividef(1.f, det);
                }
                __syncwarp(0xffffu);
                sSi[m][n] = scof[n][m] * srdet;   // Sinv = adj(S)/det
                __syncwarp(0xffffu);
                // SiH[n][jb..jb+3], n = tid&3, jb = (tid>>2)*4
                {
                    int n2 = tid & 3, jb = (tid >> 2) << 2;
#pragma unroll
                    for (int q = 0; q < 4; q++) {
                        float acc = 0.f;
#pragma unroll
                        for (int mm = 0; mm < 4; mm++)
                            acc = fmaf(sSi[n2][mm], sH[mm][jb + q], acc);
                        sSiH[n2][jb + q] = acc;
                    }
                }
                // SiR[tid>>2][tid&3]
                {
                    int n2 = tid >> 2, m2 = tid & 3;
                    float acc = 0.f;
#pragma unroll
                    for (int p = 0; p < 4; p++) acc = fmaf(sSi[n2][p], sR[p][m2], acc);
                    sSiR[n2][m2] = acc;
                }
            }
            if (tid >= 64 && tid < 128) {
                int ii = (tid - 64) >> 2, n = (tid - 64) & 3;
                float a0 = 0.f, a1 = 0.f, a2 = 0.f, a3 = 0.f;
#pragma unroll
                for (int k = 0; k < 16; k += 4) {
                    a0 = fmaf(sF[ii][k + 0], sHP[n][k + 0], a0);
                    a1 = fmaf(sF[ii][k + 1], sHP[n][k + 1], a1);
                    a2 = fmaf(sF[ii][k + 2], sHP[n][k + 2], a2);
                    a3 = fmaf(sF[ii][k + 3], sHP[n][k + 3], a3);
                }
                sFHP[ii][n] = (a0 + a1) + (a2 + a3);
            }
            __syncthreads();

            // stage3: A = F - FHP*SiH (all) ; L = FHP*Si (64..127) ; LR = FHP*SiR (128..191)
            {
                float a = sF[i][j];
#pragma unroll
                for (int n = 0; n < 4; n++) a = fmaf(-sFHP[i][n], sSiH[n][j], a);
                sA[i][j] = a;
            }
            if (tid >= 64 && tid < 128) {
                int ii = (tid - 64) >> 2, m = (tid - 64) & 3;
                float acc = 0.f;
#pragma unroll
                for (int n = 0; n < 4; n++) acc = fmaf(sFHP[ii][n], sSi[n][m], acc);
                sL[ii][m] = acc;
            } else if (tid >= 128 && tid < 192) {
                int ii = (tid - 128) >> 2, m = (tid - 128) & 3;
                float acc = 0.f;
#pragma unroll
                for (int n = 0; n < 4; n++) acc = fmaf(sFHP[ii][n], sSiR[n][m], acc);
                sLR[ii][m] = acc;
            }
            __syncthreads();

            // stage4: T1 = A P (all) ; HA = H A (tid<64) ; HB = H L (64..79)
            {
                float a0 = 0.f, a1 = 0.f, a2 = 0.f, a3 = 0.f;
#pragma unroll
                for (int k = 0; k < 16; k += 4) {
                    a0 = fmaf(sA[i][k + 0], sP[k + 0][j], a0);
                    a1 = fmaf(sA[i][k + 1], sP[k + 1][j], a1);
                    a2 = fmaf(sA[i][k + 2], sP[k + 2][j], a2);
                    a3 = fmaf(sA[i][k + 3], sP[k + 3][j], a3);
                }
                sT[i][j] = (a0 + a1) + (a2 + a3);
            }
            if (tid < 64) {
                int m = tid >> 4, jj = tid & 15;
                float acc = 0.f;
#pragma unroll
                for (int k = 0; k < 16; k++) acc = fmaf(sH[m][k], sA[k][jj], acc);
                sHA[m][jj] = acc;
            } else if (tid < 80) {
                int m = (tid - 64) >> 2, n = (tid - 64) & 3;
                float acc = 0.f;
#pragma unroll
                for (int k = 0; k < 16; k++) acc = fmaf(sH[m][k], sL[k][n], acc);
                sHB[m][n] = acc;
            }
            __syncthreads();

            // stage5: P' = T1 A^T + LR L^T + Q ; store blob[t] ; convergence
            int flag;
            {
                float a0 = sQ[i][j], a1 = 0.f, a2 = 0.f, a3 = 0.f;
#pragma unroll
                for (int k = 0; k < 16; k += 4) {
                    a0 = fmaf(sT[i][k + 0], sA[j][k + 0], a0);
                    a1 = fmaf(sT[i][k + 1], sA[j][k + 1], a1);
                    a2 = fmaf(sT[i][k + 2], sA[j][k + 2], a2);
                    a3 = fmaf(sT[i][k + 3], sA[j][k + 3], a3);
                }
                float acc = (a0 + a1) + (a2 + a3);
#pragma unroll
                for (int m = 0; m < 4; m++) acc = fmaf(sLR[i][m], sL[j][m], acc);
                float* base = blob + t * 400;
                int c4 = j >> 2, w = j & 3;
                base[(c4 * 20 + i) * 4 + w] = sA[i][j];
                if (j < 4) base[(4 * 20 + i) * 4 + j] = sL[i][j];
                if (i < 4) base[(c4 * 20 + 16 + i) * 4 + w] = sHA[i][j];
                if (i < 4 && j < 4) base[(4 * 20 + 16 + i) * 4 + j] = sHB[i][j];
                float oldp = sP[i][j];
                flag = !(fabsf(acc - oldp) <= 1e-5f * fabsf(acc) + 1e-6f);
                sP[i][j] = acc;
            }
            if (!__syncthreads_or(flag)) {
                // converged: replicate fixed-point map for remaining steps
                int c4 = j >> 2, w = j & 15 & 3;
                for (int t2 = t + 1; t2 < NSTEP; ++t2) {
                    float* b2 = blob + t2 * 400;
                    b2[(c4 * 20 + i) * 4 + w] = sA[i][j];
                    if (j < 4) b2[(4 * 20 + i) * 4 + j] = sL[i][j];
                    if (i < 4) b2[(c4 * 20 + 16 + i) * 4 + w] = sHA[i][j];
                    if (i < 4 && j < 4) b2[(4 * 20 + 16 + i) * 4 + j] = sHB[i][j];
                }
                __syncthreads();
                if (tid == 0) {
                    __threadfence();
                    *(volatile int*)&g_ready = NCHUNK;
                }
                return;
            }
            if (((t + 1) % CH) == 0) {
                if (tid == 0) {
                    __threadfence();
                    *(volatile int*)&g_ready = (t + 1) / CH;
                }
            }
        }
        return;
    }

    // ==================== CONSUMERS: warp-per-batch scan =====================
    const int lane = tid & 31;
    const int b = ((blockIdx.x - 1) << 3) + (tid >> 5);
    const int g = (lane < 20) ? lane : 0;

    // wait for chunk 0 (also guarantees g_s0/g_y0 visible)
    if (tid == 0) {
        while (*(volatile int*)&g_ready < 1) __nanosleep(200);
        __threadfence();
    }
    __syncthreads();

    float x = (lane < 16) ? g_s0[lane] : 0.f;
    float* op = out + b * (NT * NM);
    const float* ip = inp + b * (NT * NM);
    if (lane >= 16 && lane < 20) op[lane - 16] = g_y0[lane - 16];

    const float4* gb = g_blob;
    int t = 0;
    float4 obn = *(const float4*)(ip);

#pragma unroll 1
    for (int c = 0; c < NCHUNK; ++c) {
        if (c > 0) {
            if (tid == 0) {
                while (*(volatile int*)&g_ready < c + 1) __nanosleep(200);
                __threadfence();
            }
            __syncthreads();
        }
        // stage chunk c into shared
#pragma unroll
        for (int r = 0; r < 6; r++) {
            int idx = tid + r * 256;
            if (idx < CHF4) sbuf[idx] = gb[c * CHF4 + idx];
        }
        __syncthreads();

        const float4* s4 = sbuf;
#pragma unroll 1
        for (int s = 0; s < CH; ++s, ++t) {
            float4 A[5];
#pragma unroll
            for (int cc = 0; cc < 5; cc++) A[cc] = s4[s * 100 + cc * 20 + g];
            float4 ob = obn;
            int tn = (t + 1 < NSTEP) ? t + 1 : t;
            obn = *(const float4*)(ip + tn * 4);
            KF_STEP(A, ob, t);
        }
        __syncthreads();  // all readers done before next chunk overwrites
    }
}

extern "C" void kernel_launch(void* const* d_in, const int* in_sizes, int n_in,
                              void* d_out, int out_size) {
    const float* inp = (const float*)d_in[0];
    const float* F   = (const float*)d_in[1];
    const float* H   = (const float*)d_in[2];
    const float* Q   = (const float*)d_in[3];
    const float* R   = (const float*)d_in[4];
    const float* x0  = (const float*)d_in[5];
    const float* sd  = (const float*)d_in[6];
    float* out = (float*)d_out;

    reset_kernel<<<1, 1>>>();
    fused_kernel<<<129, 256>>>(inp, out, F, H, Q, R, x0, sd);
}